// round 2
// baseline (speedup 1.0000x reference)
#include <cuda_runtime.h>
#include <math.h>

// Problem constants
#define BATCH 4
#define NSEQ  4096
#define DIM   512
#define KH    64
#define MTOT  (BATCH*NSEQ)      // 16384
#define NCH   256               // prefix-scan chunks per batch
#define CHLEN (NSEQ/NCH)        // 16

// ---------------- scratch (device globals) ------------------------------------------
__device__ __align__(16) float g_h[MTOT*KH];          // 4 MB projected feats
__device__ float g_t1[MTOT];
__device__ float g_t2[MTOT];
__device__ float g_t2s[BATCH][NSEQ];                  // t2 sorted descending
__device__ int   g_perm[BATCH][NSEQ];
__device__ float g_e1[BATCH][NSEQ];                   // exp(t2s - m2)
__device__ float g_e2[BATCH][NSEQ];                   // exp(0.2*(t2s - m2))
__device__ __align__(16) float g_A[BATCH][NSEQ+1][KH];   // prefix of e1*h (desc order)
__device__ __align__(16) float g_B[BATCH][NSEQ+1][KH];   // prefix of e2*h
__device__ float g_Z1[BATCH][NSEQ+1];
__device__ float g_Z2[BATCH][NSEQ+1];
__device__ float g_tot1[BATCH][NCH][KH];
__device__ float g_tot2[BATCH][NCH][KH];
__device__ float g_totz1[BATCH][NCH];
__device__ float g_totz2[BATCH][NCH];
__device__ float g_off1[BATCH][NCH][KH];
__device__ float g_off2[BATCH][NCH][KH];
__device__ float g_offz1[BATCH][NCH];
__device__ float g_offz2[BATCH][NCH];

// ---------------- K1: h = x @ Wa^T, fused t1/t2 epilogue -----------------------------
// Block tile 128(M) x 64(K), d-chunks of 16. 256 threads, 8x4 outputs/thread.
__global__ void k_gemm(const float* __restrict__ x, const float* __restrict__ Wa,
                       const float* __restrict__ Wb, const float* __restrict__ wb_bias,
                       const float* __restrict__ Wc, const float* __restrict__ wc_bias) {
    __shared__ __align__(16) float Xs[16*132];   // [dd][m], padded 132
    __shared__ __align__(16) float Ws[16*64];    // [dd][k]
    const int t  = threadIdx.x;          // 0..255
    const int m0 = blockIdx.x * 128;
    const int tm = t >> 4;               // 0..15 -> rows tm*8..tm*8+7
    const int tk = t & 15;               // 0..15 -> cols tk*4..tk*4+3

    float acc[8][4];
#pragma unroll
    for (int i = 0; i < 8; i++) { acc[i][0]=0.f; acc[i][1]=0.f; acc[i][2]=0.f; acc[i][3]=0.f; }

    for (int d0 = 0; d0 < DIM; d0 += 16) {
#pragma unroll
        for (int l = 0; l < 2; l++) {
            int q  = t + l*256;
            int dg = q & 3;
            int m  = q >> 2;
            float4 v = *reinterpret_cast<const float4*>(x + (size_t)(m0+m)*DIM + d0 + dg*4);
            Xs[(dg*4+0)*132 + m] = v.x;
            Xs[(dg*4+1)*132 + m] = v.y;
            Xs[(dg*4+2)*132 + m] = v.z;
            Xs[(dg*4+3)*132 + m] = v.w;
        }
        {
            int dg = t & 3;
            int k  = t >> 2;
            float4 v = *reinterpret_cast<const float4*>(Wa + (size_t)k*DIM + d0 + dg*4);
            Ws[(dg*4+0)*64 + k] = v.x;
            Ws[(dg*4+1)*64 + k] = v.y;
            Ws[(dg*4+2)*64 + k] = v.z;
            Ws[(dg*4+3)*64 + k] = v.w;
        }
        __syncthreads();
#pragma unroll
        for (int dd = 0; dd < 16; dd++) {
            float4 x0 = *reinterpret_cast<const float4*>(Xs + dd*132 + tm*8);
            float4 x1 = *reinterpret_cast<const float4*>(Xs + dd*132 + tm*8 + 4);
            float4 wv = *reinterpret_cast<const float4*>(Ws + dd*64 + tk*4);
            float xv[8] = {x0.x,x0.y,x0.z,x0.w,x1.x,x1.y,x1.z,x1.w};
#pragma unroll
            for (int i = 0; i < 8; i++) {
                acc[i][0] += xv[i]*wv.x;
                acc[i][1] += xv[i]*wv.y;
                acc[i][2] += xv[i]*wv.z;
                acc[i][3] += xv[i]*wv.w;
            }
        }
        __syncthreads();
    }
    // store h
#pragma unroll
    for (int i = 0; i < 8; i++) {
        int m = m0 + tm*8 + i;
        *reinterpret_cast<float4*>(g_h + (size_t)m*KH + tk*4) =
            make_float4(acc[i][0],acc[i][1],acc[i][2],acc[i][3]);
    }
    // fused t1/t2: per-row dot with Wb, Wc, reduced over the 16 tk lanes (half-warp)
    float wbv[4], wcv[4];
#pragma unroll
    for (int c = 0; c < 4; c++) { wbv[c] = Wb[tk*4+c]; wcv[c] = Wc[tk*4+c]; }
#pragma unroll
    for (int i = 0; i < 8; i++) {
        float pb = acc[i][0]*wbv[0] + acc[i][1]*wbv[1] + acc[i][2]*wbv[2] + acc[i][3]*wbv[3];
        float pc = acc[i][0]*wcv[0] + acc[i][1]*wcv[1] + acc[i][2]*wcv[2] + acc[i][3]*wcv[3];
#pragma unroll
        for (int s = 8; s; s >>= 1) {
            pb += __shfl_xor_sync(0xFFFFFFFFu, pb, s);
            pc += __shfl_xor_sync(0xFFFFFFFFu, pc, s);
        }
        if (tk == 0) {
            int m = m0 + tm*8 + i;
            g_t1[m] = pb + wb_bias[0];
            g_t2[m] = pc + wc_bias[0];
        }
    }
}

// ---------------- K3: per-batch bitonic sort (packed u64, warp stages) ---------------
__device__ __forceinline__ unsigned int fmap(float f) {
    unsigned int u = __float_as_uint(f);
    return (u & 0x80000000u) ? ~u : (u | 0x80000000u);   // monotone ascending map
}
__device__ __forceinline__ float funmap(unsigned int u) {
    u = (u & 0x80000000u) ? (u & 0x7FFFFFFFu) : ~u;
    return __uint_as_float(u);
}

__global__ void k_sort() {
    __shared__ unsigned long long sv[NSEQ];   // 32 KB
    int b = blockIdx.x, tid = threadIdx.x;    // 1024 threads
    for (int r = tid; r < NSEQ; r += 1024) {
        unsigned int u = fmap(g_t2[b*NSEQ + r]);
        sv[r] = ((unsigned long long)u << 32) | (unsigned int)r;
    }
    __syncthreads();
    int lane = tid & 31, warp = tid >> 5;     // 32 warps
    for (int k = 2; k <= NSEQ; k <<= 1) {
        // smem stages: s >= 32
        for (int s = k >> 1; s >= 32; s >>= 1) {
#pragma unroll 1
            for (int t = tid; t < NSEQ/2; t += 1024) {
                int i = ((t & ~(s-1)) << 1) | (t & (s-1));
                int j = i + s;
                bool desc = ((i & k) == 0);
                unsigned long long a = sv[i], c = sv[j];
                bool sw = desc ? (a < c) : (a > c);
                if (sw) { sv[i] = c; sv[j] = a; }
            }
            __syncthreads();
        }
        // register stages: s = min(k/2,16) .. 1, via shfl on 32-element groups
        {
            int smax = ((k >> 1) < 32) ? (k >> 1) : 16;
#pragma unroll 1
            for (int g = warp; g < NSEQ/32; g += 32) {   // 4 groups per warp
                int i = g*32 + lane;
                unsigned long long val = sv[i];
                bool desc = ((i & k) == 0);
#pragma unroll 1
                for (int s = smax; s >= 1; s >>= 1) {
                    unsigned long long other = __shfl_xor_sync(0xFFFFFFFFu, val, s);
                    bool upper = (lane & s) != 0;
                    bool takeMax = (upper != desc);
                    bool otherBigger = (other > val);
                    val = (takeMax == otherBigger) ? other : val;
                }
                sv[i] = val;
            }
            __syncthreads();
        }
    }
    float m2 = funmap((unsigned int)(sv[0] >> 32));
    for (int r = tid; r < NSEQ; r += 1024) {
        unsigned long long pv = sv[r];
        float val = funmap((unsigned int)(pv >> 32));
        g_t2s[b][r]  = val;
        g_perm[b][r] = (int)(pv & 0xFFFFFFFFu);
        g_e1[b][r]   = expf(val - m2);
        g_e2[b][r]   = expf(0.2f*(val - m2));
    }
}

// ---------------- K4a: per-chunk totals ----------------------------------------------
__global__ void k_psum_a() {
    int b = blockIdx.x >> 8;              // NCH=256
    int c = blockIdx.x & 255;
    int k = threadIdx.x;                  // 64 threads
    int r0 = c * CHLEN;
    float s1=0.f, s2=0.f, z1=0.f, z2=0.f;
#pragma unroll
    for (int r = r0; r < r0 + CHLEN; r++) {
        float e1 = g_e1[b][r], e2 = g_e2[b][r];
        int   j  = g_perm[b][r];
        float hv = g_h[((size_t)b*NSEQ + j)*KH + k];
        s1 += e1*hv;  s2 += e2*hv;
        z1 += e1;     z2 += e2;
    }
    g_tot1[b][c][k] = s1;  g_tot2[b][c][k] = s2;
    if (k == 0) { g_totz1[b][c] = z1; g_totz2[b][c] = z2; }
}

// ---------------- K4b: exclusive scan of chunk totals --------------------------------
__global__ void k_scan() {
    int tid = threadIdx.x;                // 256 threads
    int b = tid >> 6, k = tid & 63;
    float s = 0.f;
#pragma unroll 8
    for (int c = 0; c < NCH; c++) { g_off1[b][c][k] = s; s += g_tot1[b][c][k]; }
    s = 0.f;
#pragma unroll 8
    for (int c = 0; c < NCH; c++) { g_off2[b][c][k] = s; s += g_tot2[b][c][k]; }
    if (tid < BATCH) {
        int bb = tid;
        float z = 0.f;
#pragma unroll 8
        for (int c = 0; c < NCH; c++) { g_offz1[bb][c] = z; z += g_totz1[bb][c]; }
        z = 0.f;
#pragma unroll 8
        for (int c = 0; c < NCH; c++) { g_offz2[bb][c] = z; z += g_totz2[bb][c]; }
    }
}

// ---------------- K4c: write full prefix arrays --------------------------------------
__global__ void k_psum_c() {
    int b = blockIdx.x >> 8;
    int c = blockIdx.x & 255;
    int k = threadIdx.x;
    int r0 = c * CHLEN;
    float s1 = g_off1[b][c][k], s2 = g_off2[b][c][k];
    float z1 = g_offz1[b][c],   z2 = g_offz2[b][c];
    if (c == 0) {
        g_A[b][0][k] = 0.f;  g_B[b][0][k] = 0.f;
        if (k == 0) { g_Z1[b][0] = 0.f; g_Z2[b][0] = 0.f; }
    }
#pragma unroll
    for (int r = r0; r < r0 + CHLEN; r++) {
        float e1 = g_e1[b][r], e2 = g_e2[b][r];
        int   j  = g_perm[b][r];
        float hv = g_h[((size_t)b*NSEQ + j)*KH + k];
        s1 += e1*hv;  s2 += e2*hv;
        g_A[b][r+1][k] = s1;
        g_B[b][r+1][k] = s2;
        z1 += e1;  z2 += e2;
        if (k == 0) { g_Z1[b][r+1] = z1; g_Z2[b][r+1] = z2; }
    }
}

// ---------------- K5: per-row output --------------------------------------------------
__global__ void k_out(float* __restrict__ out, const float* __restrict__ bias) {
    __shared__ int   sp[4];
    __shared__ float sc1[4], sc2[4];
    int t   = threadIdx.x;                // 256 = 4 rows x 64 k
    int rl  = t >> 6;                     // row within block
    int row = blockIdx.x*4 + rl;
    int k   = t & 63;
    int b   = row >> 12;

    if (k == 0) {
        float t1v = g_t1[row];
        float m2  = g_t2s[b][0];
        float u   = t1v + m2;
        float M   = (u > 0.f) ? u : 0.2f*u;
        sc1[rl]  = expf(u - M);
        sc2[rl]  = expf(0.2f*u - M);
        float tau = -t1v;
        int lo = 0, hi = NSEQ;
        while (lo < hi) {
            int mid = (lo + hi) >> 1;
            if (g_t2s[b][mid] > tau) lo = mid + 1; else hi = mid;
        }
        sp[rl] = lo;
    }
    __syncthreads();
    int p = sp[rl];
    float c1 = sc1[rl], c2 = sc2[rl];

    float Btot  = g_B[b][NSEQ][k];
    float Z2tot = g_Z2[b][NSEQ];
    float num = c1*g_A[b][p][k] + c2*(Btot  - g_B[b][p][k]);
    float den = c1*g_Z1[b][p]   + c2*(Z2tot - g_Z2[b][p]);
    out[(size_t)row*KH + k] = num/den + bias[k];
}

// ---------------- launch ---------------------------------------------------------------
extern "C" void kernel_launch(void* const* d_in, const int* in_sizes, int n_in,
                              void* d_out, int out_size) {
    const float* x       = (const float*)d_in[0];
    const float* Wa      = (const float*)d_in[1];
    const float* Wb      = (const float*)d_in[2];
    const float* wb_bias = (const float*)d_in[3];
    const float* Wc      = (const float*)d_in[4];
    const float* wc_bias = (const float*)d_in[5];
    const float* bias    = (const float*)d_in[6];
    float* out = (float*)d_out;

    k_gemm  <<<MTOT/128, 256>>>(x, Wa, Wb, wb_bias, Wc, wc_bias);
    k_sort  <<<BATCH,   1024>>>();
    k_psum_a<<<BATCH*NCH,  64>>>();
    k_scan  <<<1,        256>>>();
    k_psum_c<<<BATCH*NCH,  64>>>();
    k_out   <<<MTOT/4,   256>>>(out, bias);
}

// round 3
// speedup vs baseline: 2.3608x; 2.3608x over previous
#include <cuda_runtime.h>
#include <math.h>

// Problem constants
#define BATCH 4
#define NSEQ  4096
#define DIM   512
#define KH    64
#define MTOT  (BATCH*NSEQ)      // 16384
#define NCH   256               // prefix-scan chunks per batch
#define CHLEN (NSEQ/NCH)        // 16

// ---------------- scratch (device globals) ------------------------------------------
__device__ __align__(16) float g_h[MTOT*KH];          // 4 MB projected feats
__device__ float g_t1[MTOT];
__device__ float g_t2[MTOT];
__device__ float g_t2s[BATCH][NSEQ];                  // t2 sorted descending
__device__ int   g_perm[BATCH][NSEQ];
__device__ float g_e1[BATCH][NSEQ];                   // exp(t2s - m2)
__device__ float g_e2[BATCH][NSEQ];                   // exp(0.2*(t2s - m2))
__device__ __align__(16) float g_A[BATCH][NSEQ+1][KH];   // prefix of e1*h (desc order)
__device__ __align__(16) float g_B[BATCH][NSEQ+1][KH];   // prefix of e2*h
__device__ float g_Z1[BATCH][NSEQ+1];
__device__ float g_Z2[BATCH][NSEQ+1];
__device__ float g_tot1[BATCH][NCH][KH];
__device__ float g_tot2[BATCH][NCH][KH];
__device__ float g_totz1[BATCH][NCH];
__device__ float g_totz2[BATCH][NCH];
__device__ float g_off1[BATCH][NCH][KH];
__device__ float g_off2[BATCH][NCH][KH];
__device__ float g_offz1[BATCH][NCH];
__device__ float g_offz2[BATCH][NCH];

// ---------------- K1: h = x @ Wa^T, fused t1/t2 epilogue -----------------------------
__global__ void k_gemm(const float* __restrict__ x, const float* __restrict__ Wa,
                       const float* __restrict__ Wb, const float* __restrict__ wb_bias,
                       const float* __restrict__ Wc, const float* __restrict__ wc_bias) {
    __shared__ __align__(16) float Xs[16*132];   // [dd][m], padded 132
    __shared__ __align__(16) float Ws[16*64];    // [dd][k]
    const int t  = threadIdx.x;          // 0..255
    const int m0 = blockIdx.x * 128;
    const int tm = t >> 4;               // 0..15 -> rows tm*8..tm*8+7
    const int tk = t & 15;               // 0..15 -> cols tk*4..tk*4+3

    float acc[8][4];
#pragma unroll
    for (int i = 0; i < 8; i++) { acc[i][0]=0.f; acc[i][1]=0.f; acc[i][2]=0.f; acc[i][3]=0.f; }

    for (int d0 = 0; d0 < DIM; d0 += 16) {
#pragma unroll
        for (int l = 0; l < 2; l++) {
            int q  = t + l*256;
            int dg = q & 3;
            int m  = q >> 2;
            float4 v = *reinterpret_cast<const float4*>(x + (size_t)(m0+m)*DIM + d0 + dg*4);
            Xs[(dg*4+0)*132 + m] = v.x;
            Xs[(dg*4+1)*132 + m] = v.y;
            Xs[(dg*4+2)*132 + m] = v.z;
            Xs[(dg*4+3)*132 + m] = v.w;
        }
        {
            int dg = t & 3;
            int k  = t >> 2;
            float4 v = *reinterpret_cast<const float4*>(Wa + (size_t)k*DIM + d0 + dg*4);
            Ws[(dg*4+0)*64 + k] = v.x;
            Ws[(dg*4+1)*64 + k] = v.y;
            Ws[(dg*4+2)*64 + k] = v.z;
            Ws[(dg*4+3)*64 + k] = v.w;
        }
        __syncthreads();
#pragma unroll
        for (int dd = 0; dd < 16; dd++) {
            float4 x0 = *reinterpret_cast<const float4*>(Xs + dd*132 + tm*8);
            float4 x1 = *reinterpret_cast<const float4*>(Xs + dd*132 + tm*8 + 4);
            float4 wv = *reinterpret_cast<const float4*>(Ws + dd*64 + tk*4);
            float xv[8] = {x0.x,x0.y,x0.z,x0.w,x1.x,x1.y,x1.z,x1.w};
#pragma unroll
            for (int i = 0; i < 8; i++) {
                acc[i][0] += xv[i]*wv.x;
                acc[i][1] += xv[i]*wv.y;
                acc[i][2] += xv[i]*wv.z;
                acc[i][3] += xv[i]*wv.w;
            }
        }
        __syncthreads();
    }
#pragma unroll
    for (int i = 0; i < 8; i++) {
        int m = m0 + tm*8 + i;
        *reinterpret_cast<float4*>(g_h + (size_t)m*KH + tk*4) =
            make_float4(acc[i][0],acc[i][1],acc[i][2],acc[i][3]);
    }
    // fused t1/t2
    float wbv[4], wcv[4];
#pragma unroll
    for (int c = 0; c < 4; c++) { wbv[c] = Wb[tk*4+c]; wcv[c] = Wc[tk*4+c]; }
#pragma unroll
    for (int i = 0; i < 8; i++) {
        float pb = acc[i][0]*wbv[0] + acc[i][1]*wbv[1] + acc[i][2]*wbv[2] + acc[i][3]*wbv[3];
        float pc = acc[i][0]*wcv[0] + acc[i][1]*wcv[1] + acc[i][2]*wcv[2] + acc[i][3]*wcv[3];
#pragma unroll
        for (int s = 8; s; s >>= 1) {
            pb += __shfl_xor_sync(0xFFFFFFFFu, pb, s);
            pc += __shfl_xor_sync(0xFFFFFFFFu, pc, s);
        }
        if (tk == 0) {
            int m = m0 + tm*8 + i;
            g_t1[m] = pb + wb_bias[0];
            g_t2[m] = pc + wc_bias[0];
        }
    }
}

// ---------------- K3: per-batch bitonic sort (packed u64, warp stages) ---------------
__device__ __forceinline__ unsigned int fmap(float f) {
    unsigned int u = __float_as_uint(f);
    return (u & 0x80000000u) ? ~u : (u | 0x80000000u);
}
__device__ __forceinline__ float funmap(unsigned int u) {
    u = (u & 0x80000000u) ? (u & 0x7FFFFFFFu) : ~u;
    return __uint_as_float(u);
}

__global__ void k_sort() {
    __shared__ unsigned long long sv[NSEQ];   // 32 KB
    int b = blockIdx.x, tid = threadIdx.x;    // 1024 threads
    for (int r = tid; r < NSEQ; r += 1024) {
        unsigned int u = fmap(g_t2[b*NSEQ + r]);
        sv[r] = ((unsigned long long)u << 32) | (unsigned int)r;
    }
    __syncthreads();
    int lane = tid & 31, warp = tid >> 5;     // 32 warps
    for (int k = 2; k <= NSEQ; k <<= 1) {
        for (int s = k >> 1; s >= 32; s >>= 1) {
#pragma unroll 1
            for (int t = tid; t < NSEQ/2; t += 1024) {
                int i = ((t & ~(s-1)) << 1) | (t & (s-1));
                int j = i + s;
                bool desc = ((i & k) == 0);
                unsigned long long a = sv[i], c = sv[j];
                bool sw = desc ? (a < c) : (a > c);
                if (sw) { sv[i] = c; sv[j] = a; }
            }
            __syncthreads();
        }
        {
            int smax = ((k >> 1) < 32) ? (k >> 1) : 16;
#pragma unroll 1
            for (int g = warp; g < NSEQ/32; g += 32) {
                int i = g*32 + lane;
                unsigned long long val = sv[i];
                bool desc = ((i & k) == 0);
#pragma unroll 1
                for (int s = smax; s >= 1; s >>= 1) {
                    unsigned long long other = __shfl_xor_sync(0xFFFFFFFFu, val, s);
                    bool upper = (lane & s) != 0;
                    bool takeMax = (upper != desc);
                    bool otherBigger = (other > val);
                    val = (takeMax == otherBigger) ? other : val;
                }
                sv[i] = val;
            }
            __syncthreads();
        }
    }
    float m2 = funmap((unsigned int)(sv[0] >> 32));
    for (int r = tid; r < NSEQ; r += 1024) {
        unsigned long long pv = sv[r];
        float val = funmap((unsigned int)(pv >> 32));
        g_t2s[b][r]  = val;
        g_perm[b][r] = (int)(pv & 0xFFFFFFFFu);
        g_e1[b][r]   = expf(val - m2);
        g_e2[b][r]   = expf(0.2f*(val - m2));
    }
}

// ---------------- K4a: per-chunk totals ----------------------------------------------
__global__ void k_psum_a() {
    int b = blockIdx.x >> 8;              // NCH=256
    int c = blockIdx.x & 255;
    int k = threadIdx.x;                  // 64 threads
    int r0 = c * CHLEN;
    float s1=0.f, s2=0.f, z1=0.f, z2=0.f;
#pragma unroll
    for (int r = r0; r < r0 + CHLEN; r++) {
        float e1 = g_e1[b][r], e2 = g_e2[b][r];
        int   j  = g_perm[b][r];
        float hv = g_h[((size_t)b*NSEQ + j)*KH + k];
        s1 += e1*hv;  s2 += e2*hv;
        z1 += e1;     z2 += e2;
    }
    g_tot1[b][c][k] = s1;  g_tot2[b][c][k] = s2;
    if (k == 0) { g_totz1[b][c] = z1; g_totz2[b][c] = z2; }
}

// ---------------- K4b: PARALLEL exclusive scan of chunk totals -----------------------
// 256 blocks (one per (b,k)), 64 threads. Warp 0 scans tot1/tot2 over c=0..255
// (8 values/lane in registers + Kogge-Stone across lanes). Warp 1 of the k==0
// blocks scans the scalar z totals the same way.
__global__ void k_scan() {
    int b = blockIdx.x >> 6, k = blockIdx.x & 63;
    int warp = threadIdx.x >> 5, lane = threadIdx.x & 31;
    if (warp == 0) {
        float v1[8], v2[8];
        float t1 = 0.f, t2 = 0.f;
#pragma unroll
        for (int i = 0; i < 8; i++) {
            int c = lane*8 + i;
            float a = g_tot1[b][c][k];
            float d = g_tot2[b][c][k];
            v1[i] = t1; t1 += a;        // exclusive within lane
            v2[i] = t2; t2 += d;
        }
        float e1 = t1, e2 = t2;
#pragma unroll
        for (int s = 1; s < 32; s <<= 1) {
            float o1 = __shfl_up_sync(0xFFFFFFFFu, e1, s);
            float o2 = __shfl_up_sync(0xFFFFFFFFu, e2, s);
            if (lane >= s) { e1 += o1; e2 += o2; }
        }
        e1 -= t1; e2 -= t2;             // exclusive across lanes
#pragma unroll
        for (int i = 0; i < 8; i++) {
            int c = lane*8 + i;
            g_off1[b][c][k] = e1 + v1[i];
            g_off2[b][c][k] = e2 + v2[i];
        }
    } else if (k == 0) {
        float v1[8], v2[8];
        float t1 = 0.f, t2 = 0.f;
#pragma unroll
        for (int i = 0; i < 8; i++) {
            int c = lane*8 + i;
            float a = g_totz1[b][c];
            float d = g_totz2[b][c];
            v1[i] = t1; t1 += a;
            v2[i] = t2; t2 += d;
        }
        float e1 = t1, e2 = t2;
#pragma unroll
        for (int s = 1; s < 32; s <<= 1) {
            float o1 = __shfl_up_sync(0xFFFFFFFFu, e1, s);
            float o2 = __shfl_up_sync(0xFFFFFFFFu, e2, s);
            if (lane >= s) { e1 += o1; e2 += o2; }
        }
        e1 -= t1; e2 -= t2;
#pragma unroll
        for (int i = 0; i < 8; i++) {
            int c = lane*8 + i;
            g_offz1[b][c] = e1 + v1[i];
            g_offz2[b][c] = e2 + v2[i];
        }
    }
}

// ---------------- K4c: write full prefix arrays --------------------------------------
__global__ void k_psum_c() {
    int b = blockIdx.x >> 8;
    int c = blockIdx.x & 255;
    int k = threadIdx.x;
    int r0 = c * CHLEN;
    float s1 = g_off1[b][c][k], s2 = g_off2[b][c][k];
    float z1 = g_offz1[b][c],   z2 = g_offz2[b][c];
    if (c == 0) {
        g_A[b][0][k] = 0.f;  g_B[b][0][k] = 0.f;
        if (k == 0) { g_Z1[b][0] = 0.f; g_Z2[b][0] = 0.f; }
    }
#pragma unroll
    for (int r = r0; r < r0 + CHLEN; r++) {
        float e1 = g_e1[b][r], e2 = g_e2[b][r];
        int   j  = g_perm[b][r];
        float hv = g_h[((size_t)b*NSEQ + j)*KH + k];
        s1 += e1*hv;  s2 += e2*hv;
        g_A[b][r+1][k] = s1;
        g_B[b][r+1][k] = s2;
        z1 += e1;  z2 += e2;
        if (k == 0) { g_Z1[b][r+1] = z1; g_Z2[b][r+1] = z2; }
    }
}

// ---------------- K5: per-row output --------------------------------------------------
__global__ void k_out(float* __restrict__ out, const float* __restrict__ bias) {
    __shared__ int   sp[4];
    __shared__ float sc1[4], sc2[4];
    int t   = threadIdx.x;                // 256 = 4 rows x 64 k
    int rl  = t >> 6;
    int row = blockIdx.x*4 + rl;
    int k   = t & 63;
    int b   = row >> 12;

    if (k == 0) {
        float t1v = g_t1[row];
        float m2  = g_t2s[b][0];
        float u   = t1v + m2;
        float M   = (u > 0.f) ? u : 0.2f*u;
        sc1[rl]  = expf(u - M);
        sc2[rl]  = expf(0.2f*u - M);
        float tau = -t1v;
        int lo = 0, hi = NSEQ;
        while (lo < hi) {
            int mid = (lo + hi) >> 1;
            if (g_t2s[b][mid] > tau) lo = mid + 1; else hi = mid;
        }
        sp[rl] = lo;
    }
    __syncthreads();
    int p = sp[rl];
    float c1 = sc1[rl], c2 = sc2[rl];

    float Btot  = g_B[b][NSEQ][k];
    float Z2tot = g_Z2[b][NSEQ];
    float num = c1*g_A[b][p][k] + c2*(Btot  - g_B[b][p][k]);
    float den = c1*g_Z1[b][p]   + c2*(Z2tot - g_Z2[b][p]);
    out[(size_t)row*KH + k] = num/den + bias[k];
}

// ---------------- launch ---------------------------------------------------------------
extern "C" void kernel_launch(void* const* d_in, const int* in_sizes, int n_in,
                              void* d_out, int out_size) {
    const float* x       = (const float*)d_in[0];
    const float* Wa      = (const float*)d_in[1];
    const float* Wb      = (const float*)d_in[2];
    const float* wb_bias = (const float*)d_in[3];
    const float* Wc      = (const float*)d_in[4];
    const float* wc_bias = (const float*)d_in[5];
    const float* bias    = (const float*)d_in[6];
    float* out = (float*)d_out;

    k_gemm  <<<MTOT/128, 256>>>(x, Wa, Wb, wb_bias, Wc, wc_bias);
    k_sort  <<<BATCH,   1024>>>();
    k_psum_a<<<BATCH*NCH,  64>>>();
    k_scan  <<<BATCH*KH,   64>>>();
    k_psum_c<<<BATCH*NCH,  64>>>();
    k_out   <<<MTOT/4,   256>>>(out, bias);
}